// round 14
// baseline (speedup 1.0000x reference)
#include <cuda_runtime.h>
#include <math.h>

// ---------------- problem constants ----------------
#define Bc   8
#define Pc   50
#define Nc   128
#define Mc   128
#define Hc   8
#define Dc   16
#define HDc  128          // H*D
#define NEc  8
#define Fc   129          // EMB+1
#define XP   132          // x-tile pitch in fused kernel (16B-aligned rows)
#define Tc   51200        // B*P*N
#define BPc  400          // B*P

typedef unsigned long long ull;

// ---------------- packed f32x2 helpers (sm_103a FFMA2) ----------------
__device__ __forceinline__ ull fma2(ull a, ull b, ull c) {
    ull d;
    asm("fma.rn.f32x2 %0, %1, %2, %3;" : "=l"(d) : "l"(a), "l"(b), "l"(c));
    return d;
}
__device__ __forceinline__ ull pack2(float x) {
    ull r;
    unsigned int xi = __float_as_uint(x);
    asm("mov.b64 %0, {%1, %1};" : "=l"(r) : "r"(xi));
    return r;
}
__device__ __forceinline__ float2 unpack2(ull v) {
    unsigned int lo, hi;
    asm("mov.b64 {%0, %1}, %2;" : "=r"(lo), "=r"(hi) : "l"(v));
    return make_float2(__uint_as_float(lo), __uint_as_float(hi));
}

// ---------------- scratch (device globals; no allocs allowed) ----------------
__device__ float g_q  [Tc * HDc];
__device__ float g_k  [Tc * HDc];
__device__ float g_v  [Tc * HDc];
__device__ float g_att[Tc * HDc];         // out_concat
__device__ float g_imp[BPc * NEc];        // per-block importance partials
__device__ float g_we [NEc * HDc];        // We[e] @ Wfinal  (8 x 128)
__device__ float g_c  [NEc];              // be[e] . Wfinal

// ---------------- 1: QKV projections — EXACT R8-passing text ----------------
// grid.x: [0,400) Q (F=128), [400,800) K (F=129), [800,1200) V (F=129)
__global__ __launch_bounds__(256) void proj_kernel(
    const float* __restrict__ nodes, const float* __restrict__ routes,
    const float* __restrict__ Wq, const float* __restrict__ Wk,
    const float* __restrict__ Wv)
{
    int part = blockIdx.x / BPc;
    int tile = blockIdx.x % BPc;
    const float* X; const float* W; float* O; int F;
    if (part == 0)      { X = nodes;  W = Wq; O = g_q; F = 128; }
    else if (part == 1) { X = routes; W = Wk; O = g_k; F = Fc;  }
    else                { X = routes; W = Wv; O = g_v; F = Fc;  }

    extern __shared__ float sm[];
    float* Ws = sm;                  // [F][128]
    float* Xs = sm + Fc * 128;       // [F][132] transposed X

    int tid = threadIdx.x;
    for (int i = tid; i < F * 128; i += 256) Ws[i] = W[i];
    const float* Xb = X + (size_t)tile * 128 * F;
    for (int i = tid; i < 128 * F; i += 256) {
        int r = i / F, f = i % F;
        Xs[f * 132 + r] = Xb[(size_t)r * F + f];
    }
    __syncthreads();

    int tx = tid & 15, ty = tid >> 4;
    int rb = ty * 8, cb = tx * 8;
    ull acc2[8][4];
#pragma unroll
    for (int i = 0; i < 8; i++)
#pragma unroll
        for (int j = 0; j < 4; j++) acc2[i][j] = 0ull;

#pragma unroll 2
    for (int f = 0; f < 128; ++f) {
        float4 t0 = *(const float4*)(Xs + f * 132 + rb);       // rb = 8*ty -> 32B aligned
        float4 t1 = *(const float4*)(Xs + f * 132 + rb + 4);
        ulonglong2 u0 = *(const ulonglong2*)(Ws + f * 128 + cb);     // pairs (b0,b1),(b2,b3)
        ulonglong2 u1 = *(const ulonglong2*)(Ws + f * 128 + cb + 4); // pairs (b4,b5),(b6,b7)
        ull b2[4] = {u0.x, u0.y, u1.x, u1.y};
        ull a2[8];
        a2[0]=pack2(t0.x); a2[1]=pack2(t0.y); a2[2]=pack2(t0.z); a2[3]=pack2(t0.w);
        a2[4]=pack2(t1.x); a2[5]=pack2(t1.y); a2[6]=pack2(t1.z); a2[7]=pack2(t1.w);
#pragma unroll
        for (int i = 0; i < 8; i++)
#pragma unroll
            for (int j = 0; j < 4; j++) acc2[i][j] = fma2(a2[i], b2[j], acc2[i][j]);
    }
    if (F > 128) {
        int f = 128;
        float4 t0 = *(const float4*)(Xs + f * 132 + rb);
        float4 t1 = *(const float4*)(Xs + f * 132 + rb + 4);
        ulonglong2 u0 = *(const ulonglong2*)(Ws + f * 128 + cb);
        ulonglong2 u1 = *(const ulonglong2*)(Ws + f * 128 + cb + 4);
        ull b2[4] = {u0.x, u0.y, u1.x, u1.y};
        ull a2[8];
        a2[0]=pack2(t0.x); a2[1]=pack2(t0.y); a2[2]=pack2(t0.z); a2[3]=pack2(t0.w);
        a2[4]=pack2(t1.x); a2[5]=pack2(t1.y); a2[6]=pack2(t1.z); a2[7]=pack2(t1.w);
#pragma unroll
        for (int i = 0; i < 8; i++)
#pragma unroll
            for (int j = 0; j < 4; j++) acc2[i][j] = fma2(a2[i], b2[j], acc2[i][j]);
    }

    float* Ob = O + (size_t)tile * 128 * HDc;
#pragma unroll
    for (int i = 0; i < 8; i++) {
        float2 p0 = unpack2(acc2[i][0]), p1 = unpack2(acc2[i][1]);
        float2 p2 = unpack2(acc2[i][2]), p3 = unpack2(acc2[i][3]);
        *(float4*)(Ob + (size_t)(rb + i) * HDc + cb)     = make_float4(p0.x, p0.y, p1.x, p1.y);
        *(float4*)(Ob + (size_t)(rb + i) * HDc + cb + 4) = make_float4(p2.x, p2.y, p3.x, p3.y);
    }
}

// ---------------- 2: attention — one block per bp, 8 heads looped ----------------
// 128 threads, thread n = query row n. Per-head body is the R8-passing full-row
// logic verbatim; only a top-of-loop barrier guards smem restaging.
__global__ __launch_bounds__(128) void attn_kernel(
    const float* __restrict__ route_mask, const float* __restrict__ ninf)
{
    extern __shared__ float sm[];
    float* Ss = sm;              // 128*129 (mask+scores, pitch 129)
    float* ks = sm + 128 * 129;  // 128*16
    float* vs = ks + 2048;       // 128*16

    int bp = blockIdx.x;
    int n = threadIdx.x;
    size_t tb = (size_t)bp * 128;
    const float* rm = route_mask + (size_t)bp * 128 * 128;

    for (int h = 0; h < Hc; ++h) {
        __syncthreads();   // all readers of previous head's Ss/ks/vs are done

        // stage mask (coalesced; L2-hot after h=0) and k/v head slices
        for (int i = n; i < 128 * 128; i += 128)
            Ss[(i >> 7) * 129 + (i & 127)] = rm[i];
        for (int i = n; i < 512; i += 128) {
            int r = i >> 2, j = i & 3;
            ((float4*)(ks + r * 16))[j] = ((const float4*)(g_k + (tb + r) * HDc + h * Dc))[j];
            ((float4*)(vs + r * 16))[j] = ((const float4*)(g_v + (tb + r) * HDc + h * Dc))[j];
        }
        __syncthreads();

        // q row n, head h
        const ulonglong2* qp = (const ulonglong2*)(g_q + (tb + n) * HDc + h * Dc);
        ulonglong2 qa = qp[0], qb = qp[1], qc = qp[2], qd = qp[3];
        ull qr2[8] = {qa.x, qa.y, qb.x, qb.y, qc.x, qc.y, qd.x, qd.y};

        // scores: full row (own Ss row only)
#pragma unroll 4
        for (int m = 0; m < 128; ++m) {
            const ulonglong2* kp = (const ulonglong2*)(ks + m * 16);   // broadcast
            ulonglong2 k0 = kp[0], k1 = kp[1], k2 = kp[2], k3 = kp[3];
            ull sa = 0ull, sb = 0ull;
            sa = fma2(qr2[0], k0.x, sa); sb = fma2(qr2[1], k0.y, sb);
            sa = fma2(qr2[2], k1.x, sa); sb = fma2(qr2[3], k1.y, sb);
            sa = fma2(qr2[4], k2.x, sa); sb = fma2(qr2[5], k2.y, sb);
            sa = fma2(qr2[6], k3.x, sa); sb = fma2(qr2[7], k3.y, sb);
            float2 fa = unpack2(sa), fb = unpack2(sb);
            float s = (fa.x + fa.y) + (fb.x + fb.y);
            Ss[n * 129 + m] = s * 0.25f + Ss[n * 129 + m];
        }

        // softmax (own row) fused with P@V — R8 logic verbatim
        float mx = -1e30f;
        for (int m = 0; m < 128; ++m) mx = fmaxf(mx, Ss[n * 129 + m]);
        float sum = 0.0f;
        ull acc2[8];
#pragma unroll
        for (int d = 0; d < 8; d++) acc2[d] = 0ull;
#pragma unroll 2
        for (int m = 0; m < 128; ++m) {
            float pe = __expf(Ss[n * 129 + m] - mx);
            sum += pe;
            ull pe2 = pack2(pe);
            const ulonglong2* vp = (const ulonglong2*)(vs + m * 16);   // broadcast
            ulonglong2 v0 = vp[0], v1 = vp[1], v2 = vp[2], v3 = vp[3];
            acc2[0] = fma2(pe2, v0.x, acc2[0]); acc2[1] = fma2(pe2, v0.y, acc2[1]);
            acc2[2] = fma2(pe2, v1.x, acc2[2]); acc2[3] = fma2(pe2, v1.y, acc2[3]);
            acc2[4] = fma2(pe2, v2.x, acc2[4]); acc2[5] = fma2(pe2, v2.y, acc2[5]);
            acc2[6] = fma2(pe2, v3.x, acc2[6]); acc2[7] = fma2(pe2, v3.y, acc2[7]);
        }
        float keep = (ninf[tb + n] == 0.0f) ? 1.0f : 0.0f;
        float inv = keep / sum;
        float* op = g_att + (tb + n) * HDc + h * Dc;
#pragma unroll
        for (int j = 0; j < 4; j++) {
            float2 pA = unpack2(acc2[2 * j]), pB = unpack2(acc2[2 * j + 1]);
            ((float4*)op)[j] = make_float4(pA.x * inv, pA.y * inv, pB.x * inv, pB.y * inv);
        }
    }
}

// ---------------- 3: precompute we = We @ Wfinal, c = be . Wfinal ----------------
__global__ __launch_bounds__(128) void prep_kernel(
    const float* __restrict__ We, const float* __restrict__ be,
    const float* __restrict__ Wf)
{
    extern __shared__ float sm[];
    float* tileS = sm;            // [128][129]
    float* wfs   = sm + 128 * Fc; // 132
    int e = blockIdx.x, tid = threadIdx.x;

    const float* Wb = We + (size_t)e * 128 * Fc;
    for (int i = tid; i < 128 * Fc; i += 128) tileS[i] = Wb[i];
    for (int i = tid; i < Fc; i += 128) wfs[i] = Wf[i];
    __syncthreads();

    float s = 0.0f;
#pragma unroll 4
    for (int o = 0; o < Fc; ++o) s += tileS[tid * Fc + o] * wfs[o];
    g_we[e * HDc + tid] = s;

    if (tid == 0) {
        float c = 0.0f;
        const float* bb = be + (size_t)e * Fc;
        for (int o = 0; o < Fc; ++o) c += bb[o] * wfs[o];
        g_c[e] = c;
    }
}

// ---------------- 4: fused gate + MoE-collapsed score + softmax ----------------
__global__ __launch_bounds__(128) void fused_kernel(
    const float* __restrict__ ninf, const float* __restrict__ Wg,
    float* __restrict__ out)
{
    int bp = blockIdx.x, n = threadIdx.x;
    extern __shared__ float sm[];
    float* Xs  = sm;                    // 128*132 (rows 16B aligned)
    float* Wgs = sm + 128 * XP;         // 8*128
    float* Wes = Wgs + NEc * HDc;       // 8*128
    float* cS  = Wes + NEc * HDc;       // 8
    float* red = cS + NEc;              // 8
    int*   sE  = (int*)(red + NEc);     // 128*2
    float* sG  = (float*)(sE + 256);    // 128*2

    const float* attb = g_att + (size_t)bp * 128 * HDc;
    for (int i = n; i < 128 * 128; i += 128)
        Xs[(i >> 7) * XP + (i & 127)] = attb[i];
    for (int i = n; i < NEc * HDc; i += 128) {
        int ee = i >> 7, f = i & 127;
        Wgs[i] = Wg[f * NEc + ee];
        Wes[i] = g_we[i];
    }
    if (n < NEc) cS[n] = g_c[n];
    __syncthreads();

    ull dg2[NEc], de2[NEc];
#pragma unroll
    for (int e = 0; e < NEc; e++) { dg2[e] = 0ull; de2[e] = 0ull; }
    const ulonglong2* xr = (const ulonglong2*)(Xs + n * XP);
#pragma unroll 2
    for (int o2 = 0; o2 < 32; ++o2) {
        ulonglong2 xv = xr[o2];
#pragma unroll
        for (int e = 0; e < NEc; e++) {
            ulonglong2 wg = ((const ulonglong2*)(Wgs + e * HDc))[o2];
            ulonglong2 we = ((const ulonglong2*)(Wes + e * HDc))[o2];
            dg2[e] = fma2(xv.x, wg.x, dg2[e]);
            dg2[e] = fma2(xv.y, wg.y, dg2[e]);
            de2[e] = fma2(xv.x, we.x, de2[e]);
            de2[e] = fma2(xv.y, we.y, de2[e]);
        }
    }
    float dg[NEc], de[NEc];
#pragma unroll
    for (int e = 0; e < NEc; e++) {
        float2 a = unpack2(dg2[e]); dg[e] = a.x + a.y;
        float2 b = unpack2(de2[e]); de[e] = b.x + b.y;
    }

    float v1 = -1e30f, v2 = -1e30f; int i1 = 0, i2 = 0;
#pragma unroll
    for (int e = 0; e < NEc; e++) {
        float v = dg[e];
        if (v > v1)      { v2 = v1; i2 = i1; v1 = v; i1 = e; }
        else if (v > v2) { v2 = v;  i2 = e; }
    }
    float e2x = __expf(v2 - v1);
    float den = 1.0f + e2x;
    float g1 = 1.0f / den, g2 = e2x / den;

    sE[n * 2 + 0] = i1; sG[n * 2 + 0] = g1;
    sE[n * 2 + 1] = i2; sG[n * 2 + 1] = g2;

    float s = g1 * (de[i1] + cS[i1]) + g2 * (de[i2] + cS[i2]);
    s = 10.0f * tanhf(s) + ninf[(size_t)bp * 128 + n];

    __syncthreads();

    if (n < NEc) {
        float imp = 0.0f;
        for (int t = 0; t < 128; ++t) {
            if (sE[t * 2 + 0] == n) imp += sG[t * 2 + 0];
            if (sE[t * 2 + 1] == n) imp += sG[t * 2 + 1];
        }
        g_imp[bp * NEc + n] = imp;
    }

    float mx = s;
#pragma unroll
    for (int off = 16; off > 0; off >>= 1)
        mx = fmaxf(mx, __shfl_xor_sync(0xffffffffu, mx, off));
    if ((n & 31) == 0) red[n >> 5] = mx;
    __syncthreads();
    mx = fmaxf(fmaxf(red[0], red[1]), fmaxf(red[2], red[3]));
    float ex = __expf(s - mx);
    float ws = ex;
#pragma unroll
    for (int off = 16; off > 0; off >>= 1)
        ws += __shfl_xor_sync(0xffffffffu, ws, off);
    if ((n & 31) == 0) red[4 + (n >> 5)] = ws;
    __syncthreads();
    float tot = red[4] + red[5] + red[6] + red[7];
    out[(size_t)bp * 128 + n] = ex / tot;
}

// ---------------- 5: moe_loss from 400x8 partials ----------------
__global__ void loss_kernel(float* __restrict__ out, int has_loss)
{
    __shared__ float part[64];
    __shared__ float impS[NEc];
    int tid = threadIdx.x;                    // 64 threads
    int e = tid & 7, seg = tid >> 3;
    float s = 0.0f;
    for (int i = seg * 50; i < (seg + 1) * 50; ++i) s += g_imp[i * NEc + e];
    part[tid] = s;
    __syncthreads();
    if (tid < NEc) {
        float imp = 0.0f;
        for (int c = 0; c < 8; ++c) imp += part[c * NEc + tid];
        impS[tid] = imp;
    }
    __syncthreads();
    if (tid == 0 && has_loss) {
        float mean = 0.0f;
        for (int i = 0; i < NEc; i++) mean += impS[i];
        mean *= (1.0f / NEc);
        float var = 0.0f;
        for (int i = 0; i < NEc; i++) { float d = impS[i] - mean; var += d * d; }
        var *= (1.0f / NEc);
        out[Tc] = var / (mean * mean + 1e-10f);
    }
}

// ---------------- launch ----------------
extern "C" void kernel_launch(void* const* d_in, const int* in_sizes, int n_in,
                              void* d_out, int out_size)
{
    const float* nodes  = (const float*)d_in[0];
    const float* routes = (const float*)d_in[1];
    const float* ninf   = (const float*)d_in[2];
    const float* rmask  = (const float*)d_in[3];
    const float* Wq     = (const float*)d_in[4];
    const float* Wk     = (const float*)d_in[5];
    const float* Wv     = (const float*)d_in[6];
    const float* Wg     = (const float*)d_in[7];
    const float* We     = (const float*)d_in[8];
    const float* be     = (const float*)d_in[9];
    const float* Wf     = (const float*)d_in[10];
    float* out = (float*)d_out;

    const int PROJ_SMEM  = (Fc * 128 + Fc * 132) * 4;                 // 134160
    const int ATTN_SMEM  = (128 * 129 + 2048 + 2048) * 4;             // 82432
    const int PREP_SMEM  = (128 * Fc + 132) * 4;                      // 66576
    const int FUSED_SMEM = (128 * XP + 2 * NEc * HDc + NEc + NEc) * 4
                           + 256 * 4 + 256 * 4;                       // 77888

    cudaFuncSetAttribute(proj_kernel,  cudaFuncAttributeMaxDynamicSharedMemorySize, PROJ_SMEM);
    cudaFuncSetAttribute(attn_kernel,  cudaFuncAttributeMaxDynamicSharedMemorySize, ATTN_SMEM);
    cudaFuncSetAttribute(prep_kernel,  cudaFuncAttributeMaxDynamicSharedMemorySize, PREP_SMEM);
    cudaFuncSetAttribute(fused_kernel, cudaFuncAttributeMaxDynamicSharedMemorySize, FUSED_SMEM);

    prep_kernel<<<NEc, 128, PREP_SMEM>>>(We, be, Wf);
    proj_kernel<<<3 * BPc, 256, PROJ_SMEM>>>(nodes, routes, Wq, Wk, Wv);
    attn_kernel<<<BPc, 128, ATTN_SMEM>>>(rmask, ninf);
    fused_kernel<<<BPc, 128, FUSED_SMEM>>>(ninf, Wg, out);
    loss_kernel<<<1, 64>>>(out, (out_size > Tc) ? 1 : 0);
}

// round 16
// speedup vs baseline: 1.2969x; 1.2969x over previous
#include <cuda_runtime.h>
#include <math.h>

// ---------------- problem constants ----------------
#define Bc   8
#define Pc   50
#define Nc   128
#define Mc   128
#define Hc   8
#define Dc   16
#define HDc  128          // H*D
#define NEc  8
#define Fc   129          // EMB+1
#define XP   132          // x-tile pitch in fused kernel (16B-aligned rows)
#define Tc   51200        // B*P*N
#define BPc  400          // B*P

typedef unsigned long long ull;

// ---------------- packed f32x2 helpers (sm_103a FFMA2) ----------------
__device__ __forceinline__ ull fma2(ull a, ull b, ull c) {
    ull d;
    asm("fma.rn.f32x2 %0, %1, %2, %3;" : "=l"(d) : "l"(a), "l"(b), "l"(c));
    return d;
}
__device__ __forceinline__ ull pack2(float x) {
    ull r;
    unsigned int xi = __float_as_uint(x);
    asm("mov.b64 %0, {%1, %1};" : "=l"(r) : "r"(xi));
    return r;
}
__device__ __forceinline__ float2 unpack2(ull v) {
    unsigned int lo, hi;
    asm("mov.b64 {%0, %1}, %2;" : "=r"(lo), "=r"(hi) : "l"(v));
    return make_float2(__uint_as_float(lo), __uint_as_float(hi));
}

// ---------------- scratch (device globals; no allocs allowed) ----------------
__device__ float g_q  [Tc * HDc];
__device__ float g_k  [Tc * HDc];
__device__ float g_v  [Tc * HDc];
__device__ float g_att[Tc * HDc];         // out_concat
__device__ float g_imp[BPc * NEc];        // per-block importance partials
__device__ float g_we [NEc * HDc];        // We[e] @ Wfinal  (8 x 128)
__device__ float g_c  [NEc];              // be[e] . Wfinal

// ---------------- 1: QKV projection — R8 arithmetic, 64-column halves ----------------
// grid = 800 per instance (400 row-tiles x 2 column halves); 256 threads.
// smem ~101KB -> 2 CTAs/SM. Arithmetic per output element is bitwise identical
// to the R8-passing proj_kernel (same f-order, same FFMA2 pairing).
// CRITICAL: output buffer selected INSIDE device code via WHICH — passing
// __device__ symbols as host-side kernel args resolves to the host shadow
// (silently "works" on GB300 via ATS and writes host memory). Never again.
template<int F, int WHICH>
__global__ __launch_bounds__(256) void proj_half(
    const float* __restrict__ X, const float* __restrict__ W)
{
    float* O = (WHICH == 0) ? g_q : (WHICH == 1) ? g_k : g_v;   // device-side resolve

    int tile = blockIdx.x >> 1;
    int ch   = blockIdx.x & 1;          // which 64-column half
    extern __shared__ float sm[];
    float* Ws = sm;                     // [F][64]  (this half's W columns)
    float* Xs = sm + F * 64;            // [F][132] transposed X (as in R8)

    int tid = threadIdx.x;
    for (int i = tid; i < F * 64; i += 256)
        Ws[i] = W[(i >> 6) * 128 + ch * 64 + (i & 63)];
    const float* Xb = X + (size_t)tile * 128 * F;
    for (int i = tid; i < 128 * F; i += 256) {
        int r = i / F, f = i % F;       // F compile-time -> mul-shift
        Xs[f * 132 + r] = Xb[(size_t)r * F + f];
    }
    __syncthreads();

    int tx = tid & 7, ty = tid >> 3;    // 8 x 32 thread grid
    int rb = ty * 4, cb = tx * 8;       // 4 rows x 8 cols per thread
    ull acc2[4][4];
#pragma unroll
    for (int i = 0; i < 4; i++)
#pragma unroll
        for (int j = 0; j < 4; j++) acc2[i][j] = 0ull;

#pragma unroll 2
    for (int f = 0; f < F; ++f) {
        float4 t0 = *(const float4*)(Xs + f * 132 + rb);              // 16B aligned
        ulonglong2 u0 = *(const ulonglong2*)(Ws + f * 64 + cb);       // 32B aligned
        ulonglong2 u1 = *(const ulonglong2*)(Ws + f * 64 + cb + 4);
        ull b2[4] = {u0.x, u0.y, u1.x, u1.y};
        ull a2[4];
        a2[0] = pack2(t0.x); a2[1] = pack2(t0.y);
        a2[2] = pack2(t0.z); a2[3] = pack2(t0.w);
#pragma unroll
        for (int i = 0; i < 4; i++)
#pragma unroll
            for (int j = 0; j < 4; j++) acc2[i][j] = fma2(a2[i], b2[j], acc2[i][j]);
    }

    float* Ob = O + (size_t)tile * 128 * HDc + ch * 64;
#pragma unroll
    for (int i = 0; i < 4; i++) {
        float2 p0 = unpack2(acc2[i][0]), p1 = unpack2(acc2[i][1]);
        float2 p2 = unpack2(acc2[i][2]), p3 = unpack2(acc2[i][3]);
        *(float4*)(Ob + (size_t)(rb + i) * HDc + cb)     = make_float4(p0.x, p0.y, p1.x, p1.y);
        *(float4*)(Ob + (size_t)(rb + i) * HDc + cb + 4) = make_float4(p2.x, p2.y, p3.x, p3.y);
    }
}

// ---------------- 2: attention per (bp, head) — EXACT R8-passing text ----------------
__global__ __launch_bounds__(128) void attn_kernel(
    const float* __restrict__ route_mask, const float* __restrict__ ninf)
{
    int bp = blockIdx.x, h = blockIdx.y;
    extern __shared__ float sm[];
    float* ks = sm;          // 128*16
    float* vs = sm + 2048;   // 128*16
    float* Ss = sm + 4096;   // 128*129

    int n = threadIdx.x;
    size_t tb = (size_t)bp * 128;

    // q row (64B aligned) -> 8 packed pairs
    const float* qp = g_q + (tb + n) * HDc + h * Dc;
    const ulonglong2* qpu = (const ulonglong2*)qp;
    ulonglong2 qa = qpu[0], qb = qpu[1], qc = qpu[2], qd = qpu[3];
    ull qr2[8] = {qa.x, qa.y, qb.x, qb.y, qc.x, qc.y, qd.x, qd.y};
    {
        const float4* kp = (const float4*)(g_k + (tb + n) * HDc + h * Dc);
        const float4* vp = (const float4*)(g_v + (tb + n) * HDc + h * Dc);
        float4* kd = (float4*)(ks + n * 16);
        float4* vd = (float4*)(vs + n * 16);
#pragma unroll
        for (int j = 0; j < 4; j++) { kd[j] = kp[j]; vd[j] = vp[j]; }
    }
    const float* rm = route_mask + (size_t)bp * 128 * 128;
    for (int i = n; i < 128 * 128; i += 128) {
        int r = i >> 7, m = i & 127;
        Ss[r * 129 + m] = rm[i];
    }
    __syncthreads();

    // scores: 8 FFMA2 per m (two independent chains)
#pragma unroll 4
    for (int m = 0; m < 128; ++m) {
        const ulonglong2* kp = (const ulonglong2*)(ks + m * 16);   // 64B aligned
        ulonglong2 k0 = kp[0], k1 = kp[1], k2 = kp[2], k3 = kp[3];
        ull sa = 0ull, sb = 0ull;
        sa = fma2(qr2[0], k0.x, sa); sb = fma2(qr2[1], k0.y, sb);
        sa = fma2(qr2[2], k1.x, sa); sb = fma2(qr2[3], k1.y, sb);
        sa = fma2(qr2[4], k2.x, sa); sb = fma2(qr2[5], k2.y, sb);
        sa = fma2(qr2[6], k3.x, sa); sb = fma2(qr2[7], k3.y, sb);
        float2 fa = unpack2(sa), fb = unpack2(sb);
        float s = (fa.x + fa.y) + (fb.x + fb.y);
        Ss[n * 129 + m] = s * 0.25f + Ss[n * 129 + m];
    }

    // softmax (own row) fused with P@V (packed accumulators)
    float mx = -1e30f;
    for (int m = 0; m < 128; ++m) mx = fmaxf(mx, Ss[n * 129 + m]);
    float sum = 0.0f;
    ull acc2[8];
#pragma unroll
    for (int d = 0; d < 8; d++) acc2[d] = 0ull;
#pragma unroll 2
    for (int m = 0; m < 128; ++m) {
        float pe = __expf(Ss[n * 129 + m] - mx);
        sum += pe;
        ull pe2 = pack2(pe);
        const ulonglong2* vp = (const ulonglong2*)(vs + m * 16);
        ulonglong2 v0 = vp[0], v1 = vp[1], v2 = vp[2], v3 = vp[3];
        acc2[0] = fma2(pe2, v0.x, acc2[0]); acc2[1] = fma2(pe2, v0.y, acc2[1]);
        acc2[2] = fma2(pe2, v1.x, acc2[2]); acc2[3] = fma2(pe2, v1.y, acc2[3]);
        acc2[4] = fma2(pe2, v2.x, acc2[4]); acc2[5] = fma2(pe2, v2.y, acc2[5]);
        acc2[6] = fma2(pe2, v3.x, acc2[6]); acc2[7] = fma2(pe2, v3.y, acc2[7]);
    }
    float keep = (ninf[tb + n] == 0.0f) ? 1.0f : 0.0f;
    float inv = keep / sum;
    float* op = g_att + (tb + n) * HDc + h * Dc;
#pragma unroll
    for (int j = 0; j < 4; j++) {
        float2 pA = unpack2(acc2[2 * j]), pB = unpack2(acc2[2 * j + 1]);
        ((float4*)op)[j] = make_float4(pA.x * inv, pA.y * inv, pB.x * inv, pB.y * inv);
    }
}

// ---------------- 3: precompute we = We @ Wfinal, c = be . Wfinal ----------------
__global__ __launch_bounds__(128) void prep_kernel(
    const float* __restrict__ We, const float* __restrict__ be,
    const float* __restrict__ Wf)
{
    extern __shared__ float sm[];
    float* tileS = sm;            // [128][129]
    float* wfs   = sm + 128 * Fc; // 132
    int e = blockIdx.x, tid = threadIdx.x;

    const float* Wb = We + (size_t)e * 128 * Fc;
    for (int i = tid; i < 128 * Fc; i += 128) tileS[i] = Wb[i];
    for (int i = tid; i < Fc; i += 128) wfs[i] = Wf[i];
    __syncthreads();

    float s = 0.0f;
#pragma unroll 4
    for (int o = 0; o < Fc; ++o) s += tileS[tid * Fc + o] * wfs[o];
    g_we[e * HDc + tid] = s;

    if (tid == 0) {
        float c = 0.0f;
        const float* bb = be + (size_t)e * Fc;
        for (int o = 0; o < Fc; ++o) c += bb[o] * wfs[o];
        g_c[e] = c;
    }
}

// ---------------- 4: fused gate + MoE-collapsed score + softmax ----------------
__global__ __launch_bounds__(128) void fused_kernel(
    const float* __restrict__ ninf, const float* __restrict__ Wg,
    float* __restrict__ out)
{
    int bp = blockIdx.x, n = threadIdx.x;
    extern __shared__ float sm[];
    float* Xs  = sm;                    // 128*132 (rows 16B aligned)
    float* Wgs = sm + 128 * XP;         // 8*128
    float* Wes = Wgs + NEc * HDc;       // 8*128
    float* cS  = Wes + NEc * HDc;       // 8
    float* red = cS + NEc;              // 8
    int*   sE  = (int*)(red + NEc);     // 128*2
    float* sG  = (float*)(sE + 256);    // 128*2

    const float* attb = g_att + (size_t)bp * 128 * HDc;
    for (int i = n; i < 128 * 128; i += 128)
        Xs[(i >> 7) * XP + (i & 127)] = attb[i];
    for (int i = n; i < NEc * HDc; i += 128) {
        int ee = i >> 7, f = i & 127;
        Wgs[i] = Wg[f * NEc + ee];
        Wes[i] = g_we[i];
    }
    if (n < NEc) cS[n] = g_c[n];
    __syncthreads();

    ull dg2[NEc], de2[NEc];
#pragma unroll
    for (int e = 0; e < NEc; e++) { dg2[e] = 0ull; de2[e] = 0ull; }
    const ulonglong2* xr = (const ulonglong2*)(Xs + n * XP);
#pragma unroll 2
    for (int o2 = 0; o2 < 32; ++o2) {
        ulonglong2 xv = xr[o2];
#pragma unroll
        for (int e = 0; e < NEc; e++) {
            ulonglong2 wg = ((const ulonglong2*)(Wgs + e * HDc))[o2];
            ulonglong2 we = ((const ulonglong2*)(Wes + e * HDc))[o2];
            dg2[e] = fma2(xv.x, wg.x, dg2[e]);
            dg2[e] = fma2(xv.y, wg.y, dg2[e]);
            de2[e] = fma2(xv.x, we.x, de2[e]);
            de2[e] = fma2(xv.y, we.y, de2[e]);
        }
    }
    float dg[NEc], de[NEc];
#pragma unroll
    for (int e = 0; e < NEc; e++) {
        float2 a = unpack2(dg2[e]); dg[e] = a.x + a.y;
        float2 b = unpack2(de2[e]); de[e] = b.x + b.y;
    }

    float v1 = -1e30f, v2 = -1e30f; int i1 = 0, i2 = 0;
#pragma unroll
    for (int e = 0; e < NEc; e++) {
        float v = dg[e];
        if (v > v1)      { v2 = v1; i2 = i1; v1 = v; i1 = e; }
        else if (v > v2) { v2 = v;  i2 = e; }
    }
    float e2x = __expf(v2 - v1);
    float den = 1.0f + e2x;
    float g1 = 1.0f / den, g2 = e2x / den;

    sE[n * 2 + 0] = i1; sG[n * 2 + 0] = g1;
    sE[n * 2 + 1] = i2; sG[n * 2 + 1] = g2;

    float s = g1 * (de[i1] + cS[i1]) + g2 * (de[i2] + cS[i2]);
    s = 10.0f * tanhf(s) + ninf[(size_t)bp * 128 + n];

    __syncthreads();

    if (n < NEc) {
        float imp = 0.0f;
        for (int t = 0; t < 128; ++t) {
            if (sE[t * 2 + 0] == n) imp += sG[t * 2 + 0];
            if (sE[t * 2 + 1] == n) imp += sG[t * 2 + 1];
        }
        g_imp[bp * NEc + n] = imp;
    }

    float mx = s;
#pragma unroll
    for (int off = 16; off > 0; off >>= 1)
        mx = fmaxf(mx, __shfl_xor_sync(0xffffffffu, mx, off));
    if ((n & 31) == 0) red[n >> 5] = mx;
    __syncthreads();
    mx = fmaxf(fmaxf(red[0], red[1]), fmaxf(red[2], red[3]));
    float ex = __expf(s - mx);
    float ws = ex;
#pragma unroll
    for (int off = 16; off > 0; off >>= 1)
        ws += __shfl_xor_sync(0xffffffffu, ws, off);
    if ((n & 31) == 0) red[4 + (n >> 5)] = ws;
    __syncthreads();
    float tot = red[4] + red[5] + red[6] + red[7];
    out[(size_t)bp * 128 + n] = ex / tot;
}

// ---------------- 5: moe_loss from 400x8 partials ----------------
__global__ void loss_kernel(float* __restrict__ out, int has_loss)
{
    __shared__ float part[64];
    __shared__ float impS[NEc];
    int tid = threadIdx.x;                    // 64 threads
    int e = tid & 7, seg = tid >> 3;
    float s = 0.0f;
    for (int i = seg * 50; i < (seg + 1) * 50; ++i) s += g_imp[i * NEc + e];
    part[tid] = s;
    __syncthreads();
    if (tid < NEc) {
        float imp = 0.0f;
        for (int c = 0; c < 8; ++c) imp += part[c * NEc + tid];
        impS[tid] = imp;
    }
    __syncthreads();
    if (tid == 0 && has_loss) {
        float mean = 0.0f;
        for (int i = 0; i < NEc; i++) mean += impS[i];
        mean *= (1.0f / NEc);
        float var = 0.0f;
        for (int i = 0; i < NEc; i++) { float d = impS[i] - mean; var += d * d; }
        var *= (1.0f / NEc);
        out[Tc] = var / (mean * mean + 1e-10f);
    }
}

// ---------------- launch ----------------
extern "C" void kernel_launch(void* const* d_in, const int* in_sizes, int n_in,
                              void* d_out, int out_size)
{
    const float* nodes  = (const float*)d_in[0];
    const float* routes = (const float*)d_in[1];
    const float* ninf   = (const float*)d_in[2];
    const float* rmask  = (const float*)d_in[3];
    const float* Wq     = (const float*)d_in[4];
    const float* Wk     = (const float*)d_in[5];
    const float* Wv     = (const float*)d_in[6];
    const float* Wg     = (const float*)d_in[7];
    const float* We     = (const float*)d_in[8];
    const float* be     = (const float*)d_in[9];
    const float* Wf     = (const float*)d_in[10];
    float* out = (float*)d_out;

    const int PROJ128_SMEM = (128 * 64 + 128 * 132) * 4;              // 100352
    const int PROJ129_SMEM = (129 * 64 + 129 * 132) * 4;              // 101136
    const int ATTN_SMEM  = (2048 + 2048 + 128 * 129) * 4;             // 82432
    const int PREP_SMEM  = (128 * Fc + 132) * 4;                      // 66576
    const int FUSED_SMEM = (128 * XP + 2 * NEc * HDc + NEc + NEc) * 4
                           + 256 * 4 + 256 * 4;                       // 77888

    cudaFuncSetAttribute(proj_half<128, 0>, cudaFuncAttributeMaxDynamicSharedMemorySize, PROJ128_SMEM);
    cudaFuncSetAttribute(proj_half<129, 1>, cudaFuncAttributeMaxDynamicSharedMemorySize, PROJ129_SMEM);
    cudaFuncSetAttribute(proj_half<129, 2>, cudaFuncAttributeMaxDynamicSharedMemorySize, PROJ129_SMEM);
    cudaFuncSetAttribute(attn_kernel,  cudaFuncAttributeMaxDynamicSharedMemorySize, ATTN_SMEM);
    cudaFuncSetAttribute(prep_kernel,  cudaFuncAttributeMaxDynamicSharedMemorySize, PREP_SMEM);
    cudaFuncSetAttribute(fused_kernel, cudaFuncAttributeMaxDynamicSharedMemorySize, FUSED_SMEM);

    prep_kernel<<<NEc, 128, PREP_SMEM>>>(We, be, Wf);
    proj_half<128, 0><<<2 * BPc, 256, PROJ128_SMEM>>>(nodes,  Wq);
    proj_half<129, 1><<<2 * BPc, 256, PROJ129_SMEM>>>(routes, Wk);
    proj_half<129, 2><<<2 * BPc, 256, PROJ129_SMEM>>>(routes, Wv);
    attn_kernel<<<dim3(BPc, Hc), 128, ATTN_SMEM>>>(rmask, ninf);
    fused_kernel<<<BPc, 128, FUSED_SMEM>>>(ninf, Wg, out);
    loss_kernel<<<1, 64>>>(out, (out_size > Tc) ? 1 : 0);
}

// round 17
// speedup vs baseline: 1.3316x; 1.0268x over previous
#include <cuda_runtime.h>
#include <math.h>

// ---------------- problem constants ----------------
#define Bc   8
#define Pc   50
#define Nc   128
#define Mc   128
#define Hc   8
#define Dc   16
#define HDc  128          // H*D
#define NEc  8
#define Fc   129          // EMB+1
#define XP   132          // x-tile pitch in fused kernel (16B-aligned rows)
#define Tc   51200        // B*P*N
#define BPc  400          // B*P

typedef unsigned long long ull;

// ---------------- packed f32x2 helpers (sm_103a FFMA2) ----------------
__device__ __forceinline__ ull fma2(ull a, ull b, ull c) {
    ull d;
    asm("fma.rn.f32x2 %0, %1, %2, %3;" : "=l"(d) : "l"(a), "l"(b), "l"(c));
    return d;
}
__device__ __forceinline__ ull pack2(float x) {
    ull r;
    unsigned int xi = __float_as_uint(x);
    asm("mov.b64 %0, {%1, %1};" : "=l"(r) : "r"(xi));
    return r;
}
__device__ __forceinline__ float2 unpack2(ull v) {
    unsigned int lo, hi;
    asm("mov.b64 {%0, %1}, %2;" : "=r"(lo), "=r"(hi) : "l"(v));
    return make_float2(__uint_as_float(lo), __uint_as_float(hi));
}

// ---------------- scratch (device globals; no allocs allowed) ----------------
__device__ float g_q  [Tc * HDc];
__device__ float g_k  [Tc * HDc];
__device__ float g_v  [Tc * HDc];
__device__ float g_att[Tc * HDc];         // out_concat
__device__ float g_imp[BPc * NEc];        // per-block importance partials
__device__ float g_we [NEc * HDc];        // We[e] @ Wfinal  (8 x 128)
__device__ float g_c  [NEc];              // be[e] . Wfinal

// ---------------- 1: QKV projection — row-major X staging, 64-row tiles ----------------
// grid = 800 per instance; 256 threads; ~100KB smem -> 2 CTAs/SM.
// X staged ROW-MAJOR with pitch 132 (16B-aligned rows): LDG coalesced,
// STS conflict-free, NO transpose. Compute unrolls f by 4: per 4 f-steps,
// 4 aligned float4 a-loads (warp-broadcast) + 8 Ws loads + 64 FFMA2.
// Per-output f-order and fma2 column pairing identical to R8/R16 -> bitwise equal.
// Output buffer resolved INSIDE device code via WHICH — passing __device__
// symbols as host-side kernel args resolves to the host shadow (silently
// "works" on GB300 via ATS and writes host memory). Never again.
template<int F, int WHICH>
__global__ __launch_bounds__(256) void proj_t2(
    const float* __restrict__ X, const float* __restrict__ W)
{
    float* O = (WHICH == 0) ? g_q : (WHICH == 1) ? g_k : g_v;   // device-side resolve

    extern __shared__ float sm[];
    float* Ws = sm;              // [F][128]
    float* Xs = sm + F * 128;    // [64][132] row-major, padded

    int tid = threadIdx.x;
    int t64 = blockIdx.x;        // 64-row tile
    const float* Xb = X + (size_t)t64 * 64 * F;

    for (int i = tid; i < F * 128; i += 256) Ws[i] = W[i];
    for (int i = tid; i < 64 * F; i += 256) {
        int r = i / F;                       // compile-time F -> mul-shift
        Xs[r * 132 + (i - r * F)] = Xb[i];   // coalesced LDG, conflict-free STS
    }
    __syncthreads();

    int tx = tid & 15, ty = tid >> 4;
    int rb = ty * 4, cb = tx * 8;            // 4 rows x 8 cols per thread
    ull acc2[4][4];
#pragma unroll
    for (int i = 0; i < 4; i++)
#pragma unroll
        for (int j = 0; j < 4; j++) acc2[i][j] = 0ull;

    for (int f4 = 0; f4 < 128; f4 += 4) {
        // 4 aligned float4 a-loads (rows rb..rb+3, f4..f4+3); warp-broadcast
        float4 av[4];
#pragma unroll
        for (int i = 0; i < 4; i++)
            av[i] = *(const float4*)(Xs + (rb + i) * 132 + f4);
        float a_sc[4][4] = {
            {av[0].x, av[0].y, av[0].z, av[0].w},
            {av[1].x, av[1].y, av[1].z, av[1].w},
            {av[2].x, av[2].y, av[2].z, av[2].w},
            {av[3].x, av[3].y, av[3].z, av[3].w}};
#pragma unroll
        for (int ff = 0; ff < 4; ++ff) {
            int f = f4 + ff;
            ulonglong2 u0 = *(const ulonglong2*)(Ws + f * 128 + cb);
            ulonglong2 u1 = *(const ulonglong2*)(Ws + f * 128 + cb + 4);
            ull b2[4] = {u0.x, u0.y, u1.x, u1.y};
#pragma unroll
            for (int i = 0; i < 4; i++) {
                ull a = pack2(a_sc[i][ff]);
                acc2[i][0] = fma2(a, b2[0], acc2[i][0]);
                acc2[i][1] = fma2(a, b2[1], acc2[i][1]);
                acc2[i][2] = fma2(a, b2[2], acc2[i][2]);
                acc2[i][3] = fma2(a, b2[3], acc2[i][3]);
            }
        }
    }
    if (F > 128) {               // tail f = 128 (constexpr-guarded)
        int f = 128;
        ulonglong2 u0 = *(const ulonglong2*)(Ws + f * 128 + cb);
        ulonglong2 u1 = *(const ulonglong2*)(Ws + f * 128 + cb + 4);
        ull b2[4] = {u0.x, u0.y, u1.x, u1.y};
#pragma unroll
        for (int i = 0; i < 4; i++) {
            ull a = pack2(Xs[(rb + i) * 132 + 128]);
            acc2[i][0] = fma2(a, b2[0], acc2[i][0]);
            acc2[i][1] = fma2(a, b2[1], acc2[i][1]);
            acc2[i][2] = fma2(a, b2[2], acc2[i][2]);
            acc2[i][3] = fma2(a, b2[3], acc2[i][3]);
        }
    }

    float* Ob = O + (size_t)t64 * 64 * HDc;
#pragma unroll
    for (int i = 0; i < 4; i++) {
        float2 p0 = unpack2(acc2[i][0]), p1 = unpack2(acc2[i][1]);
        float2 p2 = unpack2(acc2[i][2]), p3 = unpack2(acc2[i][3]);
        *(float4*)(Ob + (size_t)(rb + i) * HDc + cb)     = make_float4(p0.x, p0.y, p1.x, p1.y);
        *(float4*)(Ob + (size_t)(rb + i) * HDc + cb + 4) = make_float4(p2.x, p2.y, p3.x, p3.y);
    }
}

// ---------------- 2: attention per (bp, head) — EXACT R8-passing text ----------------
__global__ __launch_bounds__(128) void attn_kernel(
    const float* __restrict__ route_mask, const float* __restrict__ ninf)
{
    int bp = blockIdx.x, h = blockIdx.y;
    extern __shared__ float sm[];
    float* ks = sm;          // 128*16
    float* vs = sm + 2048;   // 128*16
    float* Ss = sm + 4096;   // 128*129

    int n = threadIdx.x;
    size_t tb = (size_t)bp * 128;

    // q row (64B aligned) -> 8 packed pairs
    const float* qp = g_q + (tb + n) * HDc + h * Dc;
    const ulonglong2* qpu = (const ulonglong2*)qp;
    ulonglong2 qa = qpu[0], qb = qpu[1], qc = qpu[2], qd = qpu[3];
    ull qr2[8] = {qa.x, qa.y, qb.x, qb.y, qc.x, qc.y, qd.x, qd.y};
    {
        const float4* kp = (const float4*)(g_k + (tb + n) * HDc + h * Dc);
        const float4* vp = (const float4*)(g_v + (tb + n) * HDc + h * Dc);
        float4* kd = (float4*)(ks + n * 16);
        float4* vd = (float4*)(vs + n * 16);
#pragma unroll
        for (int j = 0; j < 4; j++) { kd[j] = kp[j]; vd[j] = vp[j]; }
    }
    const float* rm = route_mask + (size_t)bp * 128 * 128;
    for (int i = n; i < 128 * 128; i += 128) {
        int r = i >> 7, m = i & 127;
        Ss[r * 129 + m] = rm[i];
    }
    __syncthreads();

    // scores: 8 FFMA2 per m (two independent chains)
#pragma unroll 4
    for (int m = 0; m < 128; ++m) {
        const ulonglong2* kp = (const ulonglong2*)(ks + m * 16);   // 64B aligned
        ulonglong2 k0 = kp[0], k1 = kp[1], k2 = kp[2], k3 = kp[3];
        ull sa = 0ull, sb = 0ull;
        sa = fma2(qr2[0], k0.x, sa); sb = fma2(qr2[1], k0.y, sb);
        sa = fma2(qr2[2], k1.x, sa); sb = fma2(qr2[3], k1.y, sb);
        sa = fma2(qr2[4], k2.x, sa); sb = fma2(qr2[5], k2.y, sb);
        sa = fma2(qr2[6], k3.x, sa); sb = fma2(qr2[7], k3.y, sb);
        float2 fa = unpack2(sa), fb = unpack2(sb);
        float s = (fa.x + fa.y) + (fb.x + fb.y);
        Ss[n * 129 + m] = s * 0.25f + Ss[n * 129 + m];
    }

    // softmax (own row) fused with P@V (packed accumulators)
    float mx = -1e30f;
    for (int m = 0; m < 128; ++m) mx = fmaxf(mx, Ss[n * 129 + m]);
    float sum = 0.0f;
    ull acc2[8];
#pragma unroll
    for (int d = 0; d < 8; d++) acc2[d] = 0ull;
#pragma unroll 2
    for (int m = 0; m < 128; ++m) {
        float pe = __expf(Ss[n * 129 + m] - mx);
        sum += pe;
        ull pe2 = pack2(pe);
        const ulonglong2* vp = (const ulonglong2*)(vs + m * 16);
        ulonglong2 v0 = vp[0], v1 = vp[1], v2 = vp[2], v3 = vp[3];
        acc2[0] = fma2(pe2, v0.x, acc2[0]); acc2[1] = fma2(pe2, v0.y, acc2[1]);
        acc2[2] = fma2(pe2, v1.x, acc2[2]); acc2[3] = fma2(pe2, v1.y, acc2[3]);
        acc2[4] = fma2(pe2, v2.x, acc2[4]); acc2[5] = fma2(pe2, v2.y, acc2[5]);
        acc2[6] = fma2(pe2, v3.x, acc2[6]); acc2[7] = fma2(pe2, v3.y, acc2[7]);
    }
    float keep = (ninf[tb + n] == 0.0f) ? 1.0f : 0.0f;
    float inv = keep / sum;
    float* op = g_att + (tb + n) * HDc + h * Dc;
#pragma unroll
    for (int j = 0; j < 4; j++) {
        float2 pA = unpack2(acc2[2 * j]), pB = unpack2(acc2[2 * j + 1]);
        ((float4*)op)[j] = make_float4(pA.x * inv, pA.y * inv, pB.x * inv, pB.y * inv);
    }
}

// ---------------- 3: precompute we = We @ Wfinal, c = be . Wfinal ----------------
__global__ __launch_bounds__(128) void prep_kernel(
    const float* __restrict__ We, const float* __restrict__ be,
    const float* __restrict__ Wf)
{
    extern __shared__ float sm[];
    float* tileS = sm;            // [128][129]
    float* wfs   = sm + 128 * Fc; // 132
    int e = blockIdx.x, tid = threadIdx.x;

    const float* Wb = We + (size_t)e * 128 * Fc;
    for (int i = tid; i < 128 * Fc; i += 128) tileS[i] = Wb[i];
    for (int i = tid; i < Fc; i += 128) wfs[i] = Wf[i];
    __syncthreads();

    float s = 0.0f;
#pragma unroll 4
    for (int o = 0; o < Fc; ++o) s += tileS[tid * Fc + o] * wfs[o];
    g_we[e * HDc + tid] = s;

    if (tid == 0) {
        float c = 0.0f;
        const float* bb = be + (size_t)e * Fc;
        for (int o = 0; o < Fc; ++o) c += bb[o] * wfs[o];
        g_c[e] = c;
    }
}

// ---------------- 4: fused gate + MoE-collapsed score + softmax ----------------
__global__ __launch_bounds__(128) void fused_kernel(
    const float* __restrict__ ninf, const float* __restrict__ Wg,
    float* __restrict__ out)
{
    int bp = blockIdx.x, n = threadIdx.x;
    extern __shared__ float sm[];
    float* Xs  = sm;                    // 128*132 (rows 16B aligned)
    float* Wgs = sm + 128 * XP;         // 8*128
    float* Wes = Wgs + NEc * HDc;       // 8*128
    float* cS  = Wes + NEc * HDc;       // 8
    float* red = cS + NEc;              // 8
    int*   sE  = (int*)(red + NEc);     // 128*2
    float* sG  = (float*)(sE + 256);    // 128*2

    const float* attb = g_att + (size_t)bp * 128 * HDc;
    for (int i = n; i < 128 * 128; i += 128)
        Xs[(i >> 7) * XP + (i & 127)] = attb[i];
    for (int i = n; i < NEc * HDc; i += 128) {
        int ee = i >> 7, f = i & 127;
        Wgs[i] = Wg[f * NEc + ee];
        Wes[i] = g_we[i];
    }
    if (n < NEc) cS[n] = g_c[n];
    __syncthreads();

    ull dg2[NEc], de2[NEc];
#pragma unroll
    for (int e = 0; e < NEc; e++) { dg2[e] = 0ull; de2[e] = 0ull; }
    const ulonglong2* xr = (const ulonglong2*)(Xs + n * XP);
#pragma unroll 2
    for (int o2 = 0; o2 < 32; ++o2) {
        ulonglong2 xv = xr[o2];
#pragma unroll
        for (int e = 0; e < NEc; e++) {
            ulonglong2 wg = ((const ulonglong2*)(Wgs + e * HDc))[o2];
            ulonglong2 we = ((const ulonglong2*)(Wes + e * HDc))[o2];
            dg2[e] = fma2(xv.x, wg.x, dg2[e]);
            dg2[e] = fma2(xv.y, wg.y, dg2[e]);
            de2[e] = fma2(xv.x, we.x, de2[e]);
            de2[e] = fma2(xv.y, we.y, de2[e]);
        }
    }
    float dg[NEc], de[NEc];
#pragma unroll
    for (int e = 0; e < NEc; e++) {
        float2 a = unpack2(dg2[e]); dg[e] = a.x + a.y;
        float2 b = unpack2(de2[e]); de[e] = b.x + b.y;
    }

    float v1 = -1e30f, v2 = -1e30f; int i1 = 0, i2 = 0;
#pragma unroll
    for (int e = 0; e < NEc; e++) {
        float v = dg[e];
        if (v > v1)      { v2 = v1; i2 = i1; v1 = v; i1 = e; }
        else if (v > v2) { v2 = v;  i2 = e; }
    }
    float e2x = __expf(v2 - v1);
    float den = 1.0f + e2x;
    float g1 = 1.0f / den, g2 = e2x / den;

    sE[n * 2 + 0] = i1; sG[n * 2 + 0] = g1;
    sE[n * 2 + 1] = i2; sG[n * 2 + 1] = g2;

    float s = g1 * (de[i1] + cS[i1]) + g2 * (de[i2] + cS[i2]);
    s = 10.0f * tanhf(s) + ninf[(size_t)bp * 128 + n];

    __syncthreads();

    if (n < NEc) {
        float imp = 0.0f;
        for (int t = 0; t < 128; ++t) {
            if (sE[t * 2 + 0] == n) imp += sG[t * 2 + 0];
            if (sE[t * 2 + 1] == n) imp += sG[t * 2 + 1];
        }
        g_imp[bp * NEc + n] = imp;
    }

    float mx = s;
#pragma unroll
    for (int off = 16; off > 0; off >>= 1)
        mx = fmaxf(mx, __shfl_xor_sync(0xffffffffu, mx, off));
    if ((n & 31) == 0) red[n >> 5] = mx;
    __syncthreads();
    mx = fmaxf(fmaxf(red[0], red[1]), fmaxf(red[2], red[3]));
    float ex = __expf(s - mx);
    float ws = ex;
#pragma unroll
    for (int off = 16; off > 0; off >>= 1)
        ws += __shfl_xor_sync(0xffffffffu, ws, off);
    if ((n & 31) == 0) red[4 + (n >> 5)] = ws;
    __syncthreads();
    float tot = red[4] + red[5] + red[6] + red[7];
    out[(size_t)bp * 128 + n] = ex / tot;
}

// ---------------- 5: moe_loss from 400x8 partials ----------------
__global__ void loss_kernel(float* __restrict__ out, int has_loss)
{
    __shared__ float part[64];
    __shared__ float impS[NEc];
    int tid = threadIdx.x;                    // 64 threads
    int e = tid & 7, seg = tid >> 3;
    float s = 0.0f;
    for (int i = seg * 50; i < (seg + 1) * 50; ++i) s += g_imp[i * NEc + e];
    part[tid] = s;
    __syncthreads();
    if (tid < NEc) {
        float imp = 0.0f;
        for (int c = 0; c < 8; ++c) imp += part[c * NEc + tid];
        impS[tid] = imp;
    }
    __syncthreads();
    if (tid == 0 && has_loss) {
        float mean = 0.0f;
        for (int i = 0; i < NEc; i++) mean += impS[i];
        mean *= (1.0f / NEc);
        float var = 0.0f;
        for (int i = 0; i < NEc; i++) { float d = impS[i] - mean; var += d * d; }
        var *= (1.0f / NEc);
        out[Tc] = var / (mean * mean + 1e-10f);
    }
}

// ---------------- launch ----------------
extern "C" void kernel_launch(void* const* d_in, const int* in_sizes, int n_in,
                              void* d_out, int out_size)
{
    const float* nodes  = (const float*)d_in[0];
    const float* routes = (const float*)d_in[1];
    const float* ninf   = (const float*)d_in[2];
    const float* rmask  = (const float*)d_in[3];
    const float* Wq     = (const float*)d_in[4];
    const float* Wk     = (const float*)d_in[5];
    const float* Wv     = (const float*)d_in[6];
    const float* Wg     = (const float*)d_in[7];
    const float* We     = (const float*)d_in[8];
    const float* be     = (const float*)d_in[9];
    const float* Wf     = (const float*)d_in[10];
    float* out = (float*)d_out;

    const int PROJ128_SMEM = (128 * 128 + 64 * 132) * 4;              // 99328
    const int PROJ129_SMEM = (129 * 128 + 64 * 132) * 4;              // 99840
    const int ATTN_SMEM  = (2048 + 2048 + 128 * 129) * 4;             // 82432
    const int PREP_SMEM  = (128 * Fc + 132) * 4;                      // 66576
    const int FUSED_SMEM = (128 * XP + 2 * NEc * HDc + NEc + NEc) * 4
                           + 256 * 4 + 256 * 4;                       // 77888

    cudaFuncSetAttribute(proj_t2<128, 0>, cudaFuncAttributeMaxDynamicSharedMemorySize, PROJ128_SMEM);
    cudaFuncSetAttribute(proj_t2<129, 1>, cudaFuncAttributeMaxDynamicSharedMemorySize, PROJ129_SMEM);
    cudaFuncSetAttribute(proj_t2<129, 2>, cudaFuncAttributeMaxDynamicSharedMemorySize, PROJ129_SMEM);
    cudaFuncSetAttribute(attn_kernel,  cudaFuncAttributeMaxDynamicSharedMemorySize, ATTN_SMEM);
    cudaFuncSetAttribute(prep_kernel,  cudaFuncAttributeMaxDynamicSharedMemorySize, PREP_SMEM);
    cudaFuncSetAttribute(fused_kernel, cudaFuncAttributeMaxDynamicSharedMemorySize, FUSED_SMEM);

    prep_kernel<<<NEc, 128, PREP_SMEM>>>(We, be, Wf);
    proj_t2<128, 0><<<2 * BPc, 256, PROJ128_SMEM>>>(nodes,  Wq);
    proj_t2<129, 1><<<2 * BPc, 256, PROJ129_SMEM>>>(routes, Wk);
    proj_t2<129, 2><<<2 * BPc, 256, PROJ129_SMEM>>>(routes, Wv);
    attn_kernel<<<dim3(BPc, Hc), 128, ATTN_SMEM>>>(rmask, ninf);
    fused_kernel<<<BPc, 128, FUSED_SMEM>>>(ninf, Wg, out);
    loss_kernel<<<1, 64>>>(out, (out_size > Tc) ? 1 : 0);
}